// round 1
// baseline (speedup 1.0000x reference)
#include <cuda_runtime.h>
#include <cuda_bf16.h>

// Gumbel-Sinkhorn via u/v diagonal-scaling form.
// X0 = exp((sigmoid(gamma)+noise - rowmax)/T); 20x { u=1/(X0 v); v=1/(X0^T u) }; out = u_i X0_ij v_j.
// One block of 64 threads per 64x64 matrix; thread t keeps row t AND column t
// of X0 register-resident as packed f32x2 pairs; u/v broadcast via shared mem.

#define EX2F(d, x)       asm("ex2.approx.f32 %0, %1;" : "=f"(d) : "f"(x))
#define RCPF(d, x)       asm("rcp.approx.f32 %0, %1;" : "=f"(d) : "f"(x))
#define PACK2(d, lo, hi) asm("mov.b64 %0, {%1, %2};" : "=l"(d) : "f"(lo), "f"(hi))
#define UNPACK2(lo, hi, s) asm("mov.b64 {%0, %1}, %2;" : "=f"(lo), "=f"(hi) : "l"(s))
#define FMA2(acc, a, b)  asm("fma.rn.f32x2 %0, %1, %2, %0;" : "+l"(acc) : "l"(a), "l"(b))
#define ADD2(d, a, b)    asm("add.rn.f32x2 %0, %1, %2;" : "=l"(d) : "l"(a), "l"(b))
#define MUL2(d, a, b)    asm("mul.rn.f32x2 %0, %1, %2;" : "=l"(d) : "l"(a), "l"(b))

__device__ float g_sig[4096];  // sigmoid(gamma), computed once per launch by pre-kernel

__global__ void sigmoid_kernel(const float* __restrict__ gamma) {
    int i = blockIdx.x * blockDim.x + threadIdx.x;
    if (i < 4096) {
        float x = gamma[i];
        float e; EX2F(e, -x * 1.4426950408889634f);   // exp(-x)
        float s; RCPF(s, 1.0f + e);                    // 1/(1+exp(-x))
        g_sig[i] = s;
    }
}

// 64-element dot product: x = 32 packed f32x2 pairs in registers,
// w = 32 packed pairs in shared memory (uniform broadcast loads).
__device__ __forceinline__ float dot64(const unsigned long long (&x)[32],
                                       const unsigned long long* __restrict__ w) {
    unsigned long long a0 = 0ull, a1 = 0ull, a2 = 0ull, a3 = 0ull;
#pragma unroll
    for (int k = 0; k < 32; k += 4) {
        unsigned long long w0 = w[k], w1 = w[k + 1], w2 = w[k + 2], w3 = w[k + 3];
        FMA2(a0, x[k + 0], w0);
        FMA2(a1, x[k + 1], w1);
        FMA2(a2, x[k + 2], w2);
        FMA2(a3, x[k + 3], w3);
    }
    unsigned long long s0, s1, s;
    ADD2(s0, a0, a1);
    ADD2(s1, a2, a3);
    ADD2(s, s0, s1);
    float lo, hi; UNPACK2(lo, hi, s);
    return lo + hi;
}

__global__ void __launch_bounds__(64) sinkhorn_kernel(const float* __restrict__ noise,
                                                      float* __restrict__ out) {
    __shared__ __align__(16) float sA[64 * 68];  // stride 68 -> conflict-free column reads
    __shared__ __align__(16) float sU[64];
    __shared__ __align__(16) float sV[64];

    const int b = blockIdx.x;
    const int t = threadIdx.x;  // 0..63

    // ---- cooperative coalesced load of noise + add sigmoid(gamma) into smem ----
    const float4* __restrict__ n4 = reinterpret_cast<const float4*>(noise) + (size_t)b * 1024;
    const float4* __restrict__ g4 = reinterpret_cast<const float4*>(g_sig);
#pragma unroll
    for (int k = 0; k < 16; k++) {
        int idx = k * 64 + t;                 // float4 index within the 64x64 tile
        float4 nv = n4[idx];
        float4 gv = g4[idx];
        float4 av = make_float4(nv.x + gv.x, nv.y + gv.y, nv.z + gv.z, nv.w + gv.w);
        int row = idx >> 4, c4 = idx & 15;    // 16 float4 per row
        *reinterpret_cast<float4*>(sA + row * 68 + c4 * 4) = av;
    }
    __syncthreads();

    // ---- thread t: read its row of a = sigmoid(gamma)+noise ----
    float a[64];
#pragma unroll
    for (int k = 0; k < 16; k++) {
        float4 v = *reinterpret_cast<const float4*>(sA + t * 68 + k * 4);
        a[4 * k + 0] = v.x; a[4 * k + 1] = v.y; a[4 * k + 2] = v.z; a[4 * k + 3] = v.w;
    }

    // row max (for numerical stabilization; absorbed into u -> result unchanged)
    float mx[8];
#pragma unroll
    for (int k = 0; k < 8; k++) {
        float mm = a[8 * k];
#pragma unroll
        for (int j = 1; j < 8; j++) mm = fmaxf(mm, a[8 * k + j]);
        mx[k] = mm;
    }
    float m = fmaxf(fmaxf(fmaxf(mx[0], mx[1]), fmaxf(mx[2], mx[3])),
                    fmaxf(fmaxf(mx[4], mx[5]), fmaxf(mx[6], mx[7])));

    // X0 row = exp2((a - m) * log2(e)/T), kept packed in regs; also row sum; write back to smem
    const float C = 14.426950408889634f;  // log2(e) / 0.1
    unsigned long long xr[32];
    float rs0 = 0.f, rs1 = 0.f, rs2 = 0.f, rs3 = 0.f;
#pragma unroll
    for (int j = 0; j < 32; j++) {
        float e0, e1;
        EX2F(e0, (a[2 * j + 0] - m) * C);
        EX2F(e1, (a[2 * j + 1] - m) * C);
        PACK2(xr[j], e0, e1);
        if ((j & 3) == 0)      rs0 += e0 + e1;
        else if ((j & 3) == 1) rs1 += e0 + e1;
        else if ((j & 3) == 2) rs2 += e0 + e1;
        else                   rs3 += e0 + e1;
        *reinterpret_cast<float2*>(sA + t * 68 + 2 * j) = make_float2(e0, e1);
    }
    __syncthreads();

    // ---- thread t: read its COLUMN of X0 (lockstep over i -> conflict-free) ----
    unsigned long long xc[32];
#pragma unroll
    for (int i = 0; i < 32; i++) {
        float c0 = sA[(2 * i + 0) * 68 + t];
        float c1 = sA[(2 * i + 1) * 68 + t];
        PACK2(xc[i], c0, c1);
    }

    // iteration 1 row-normalize is just 1/rowsum (v starts at all-ones)
    float rsum = (rs0 + rs1) + (rs2 + rs3);
    float u; RCPF(u, rsum);
    sU[t] = u;
    __syncthreads();

    const unsigned long long* sU2 = reinterpret_cast<const unsigned long long*>(sU);
    const unsigned long long* sV2 = reinterpret_cast<const unsigned long long*>(sV);

    // 20 iterations total: u-updates = 1 (above) + 19 (loop); v-updates = 19 (loop) + 1 (tail)
#pragma unroll 1
    for (int it = 0; it < 19; ++it) {
        float z = dot64(xc, sU2);       // (X0^T u)_t
        float v; RCPF(v, z);
        sV[t] = v;
        __syncthreads();
        float y = dot64(xr, sV2);       // (X0 v)_t
        RCPF(u, y);
        sU[t] = u;
        __syncthreads();
    }
    {
        float z = dot64(xc, sU2);       // final column normalization (20th)
        float v; RCPF(v, z);
        sV[t] = v;
        __syncthreads();
    }

    // ---- epilogue: out[t][j] = u_t * X0[t][j] * v_j ----
    unsigned long long u2; PACK2(u2, u, u);
    float4* __restrict__ o4 = reinterpret_cast<float4*>(out) + (size_t)b * 1024 + t * 16;
#pragma unroll
    for (int k = 0; k < 16; k++) {
        unsigned long long w0 = sV2[2 * k], w1 = sV2[2 * k + 1];
        unsigned long long p0, p1;
        MUL2(p0, xr[2 * k + 0], w0);
        MUL2(p0, p0, u2);
        MUL2(p1, xr[2 * k + 1], w1);
        MUL2(p1, p1, u2);
        float4 o;
        UNPACK2(o.x, o.y, p0);
        UNPACK2(o.z, o.w, p1);
        o4[k] = o;
    }
}

extern "C" void kernel_launch(void* const* d_in, const int* in_sizes, int n_in,
                              void* d_out, int out_size) {
    const float* gamma = (const float*)d_in[0];
    const float* noise = (const float*)d_in[1];
    int s0 = in_sizes[0], s1 = (n_in >= 2) ? in_sizes[1] : 0;
    if (s0 > s1) {  // defensive: gamma is the small one (4096 elements)
        const float* tmp = gamma; gamma = noise; noise = tmp;
        int ts = s0; s0 = s1; s1 = ts;
    }
    int num_matrices = s1 / 4096;  // 8192 for the reference shapes
    float* out = (float*)d_out;

    sigmoid_kernel<<<16, 256>>>(gamma);
    sinkhorn_kernel<<<num_matrices, 64>>>(noise, out);
}

// round 2
// speedup vs baseline: 1.0004x; 1.0004x over previous
#include <cuda_runtime.h>
#include <cuda_bf16.h>

// Gumbel-Sinkhorn via u/v diagonal-scaling form.
// X0 = exp((sigmoid(gamma)+noise - rowmax)/T); 20x { u=1/(X0 v); v=1/(X0^T u) }; out = u_i X0_ij v_j.
// One block of 64 threads per 64x64 matrix; thread t keeps row t AND column t
// of X0 register-resident as packed f32x2 pairs; u/v broadcast via shared mem
// with LDS.128 (ulonglong2) loads: 16 LDS + 32 FFMA2 per 64-dot.

#define EX2F(d, x)       asm("ex2.approx.f32 %0, %1;" : "=f"(d) : "f"(x))
#define RCPF(d, x)       asm("rcp.approx.f32 %0, %1;" : "=f"(d) : "f"(x))
#define PACK2(d, lo, hi) asm("mov.b64 %0, {%1, %2};" : "=l"(d) : "f"(lo), "f"(hi))
#define UNPACK2(lo, hi, s) asm("mov.b64 {%0, %1}, %2;" : "=f"(lo), "=f"(hi) : "l"(s))
#define FMA2(acc, a, b)  asm("fma.rn.f32x2 %0, %1, %2, %0;" : "+l"(acc) : "l"(a), "l"(b))
#define ADD2(d, a, b)    asm("add.rn.f32x2 %0, %1, %2;" : "=l"(d) : "l"(a), "l"(b))
#define MUL2(d, a, b)    asm("mul.rn.f32x2 %0, %1, %2;" : "=l"(d) : "l"(a), "l"(b))

__device__ float g_sig[4096];  // sigmoid(gamma), computed once per launch by pre-kernel

__global__ void sigmoid_kernel(const float* __restrict__ gamma) {
    int i = blockIdx.x * blockDim.x + threadIdx.x;
    if (i < 4096) {
        float x = gamma[i];
        float e; EX2F(e, -x * 1.4426950408889634f);   // exp(-x)
        float s; RCPF(s, 1.0f + e);                    // 1/(1+exp(-x))
        g_sig[i] = s;
    }
}

// 64-element dot: x = 32 packed f32x2 pairs in registers,
// w = 16 ulonglong2 (LDS.128 uniform broadcast) from shared memory.
__device__ __forceinline__ float dot64(const unsigned long long (&x)[32],
                                       const ulonglong2* __restrict__ w) {
    unsigned long long a0 = 0ull, a1 = 0ull, a2 = 0ull, a3 = 0ull;
#pragma unroll
    for (int k = 0; k < 16; k += 2) {
        ulonglong2 wa = w[k];
        ulonglong2 wb = w[k + 1];
        FMA2(a0, x[2 * k + 0], wa.x);
        FMA2(a1, x[2 * k + 1], wa.y);
        FMA2(a2, x[2 * k + 2], wb.x);
        FMA2(a3, x[2 * k + 3], wb.y);
    }
    unsigned long long s0, s1, s;
    ADD2(s0, a0, a1);
    ADD2(s1, a2, a3);
    ADD2(s, s0, s1);
    float lo, hi; UNPACK2(lo, hi, s);
    return lo + hi;
}

__global__ void __launch_bounds__(64) sinkhorn_kernel(const float* __restrict__ noise,
                                                      float* __restrict__ out) {
    __shared__ __align__(16) float sA[64 * 68];  // stride 68 -> conflict-free column reads
    __shared__ __align__(16) float sU[64];
    __shared__ __align__(16) float sV[64];

    const int b = blockIdx.x;
    const int t = threadIdx.x;  // 0..63

    // ---- cooperative coalesced load of noise + add sigmoid(gamma) into smem ----
    const float4* __restrict__ n4 = reinterpret_cast<const float4*>(noise) + (size_t)b * 1024;
    const float4* __restrict__ g4 = reinterpret_cast<const float4*>(g_sig);
#pragma unroll
    for (int k = 0; k < 16; k++) {
        int idx = k * 64 + t;                 // float4 index within the 64x64 tile
        float4 nv = n4[idx];
        float4 gv = g4[idx];
        float4 av = make_float4(nv.x + gv.x, nv.y + gv.y, nv.z + gv.z, nv.w + gv.w);
        int row = idx >> 4, c4 = idx & 15;    // 16 float4 per row
        *reinterpret_cast<float4*>(sA + row * 68 + c4 * 4) = av;
    }
    __syncthreads();

    // ---- thread t: read its row of a = sigmoid(gamma)+noise ----
    float a[64];
#pragma unroll
    for (int k = 0; k < 16; k++) {
        float4 v = *reinterpret_cast<const float4*>(sA + t * 68 + k * 4);
        a[4 * k + 0] = v.x; a[4 * k + 1] = v.y; a[4 * k + 2] = v.z; a[4 * k + 3] = v.w;
    }

    // row max (for numerical stabilization; absorbed into u -> result unchanged)
    float mx[8];
#pragma unroll
    for (int k = 0; k < 8; k++) {
        float mm = a[8 * k];
#pragma unroll
        for (int j = 1; j < 8; j++) mm = fmaxf(mm, a[8 * k + j]);
        mx[k] = mm;
    }
    float m = fmaxf(fmaxf(fmaxf(mx[0], mx[1]), fmaxf(mx[2], mx[3])),
                    fmaxf(fmaxf(mx[4], mx[5]), fmaxf(mx[6], mx[7])));

    // X0 row = exp2((a - m) * log2(e)/T), kept packed in regs; also row sum; write back to smem
    const float C = 14.426950408889634f;  // log2(e) / 0.1
    unsigned long long xr[32];
    float rs0 = 0.f, rs1 = 0.f, rs2 = 0.f, rs3 = 0.f;
#pragma unroll
    for (int j = 0; j < 32; j++) {
        float e0, e1;
        EX2F(e0, (a[2 * j + 0] - m) * C);
        EX2F(e1, (a[2 * j + 1] - m) * C);
        PACK2(xr[j], e0, e1);
        if ((j & 3) == 0)      rs0 += e0 + e1;
        else if ((j & 3) == 1) rs1 += e0 + e1;
        else if ((j & 3) == 2) rs2 += e0 + e1;
        else                   rs3 += e0 + e1;
        *reinterpret_cast<float2*>(sA + t * 68 + 2 * j) = make_float2(e0, e1);
    }
    __syncthreads();

    // ---- thread t: read its COLUMN of X0 (lockstep over i -> conflict-free) ----
    unsigned long long xc[32];
#pragma unroll
    for (int i = 0; i < 32; i++) {
        float c0 = sA[(2 * i + 0) * 68 + t];
        float c1 = sA[(2 * i + 1) * 68 + t];
        PACK2(xc[i], c0, c1);
    }

    // iteration 1 row-normalize is just 1/rowsum (v starts at all-ones)
    float rsum = (rs0 + rs1) + (rs2 + rs3);
    float u; RCPF(u, rsum);
    sU[t] = u;
    __syncthreads();

    const ulonglong2* sU2 = reinterpret_cast<const ulonglong2*>(sU);
    const ulonglong2* sV2 = reinterpret_cast<const ulonglong2*>(sV);

    // 20 iterations total: u-updates = 1 (above) + 19 (loop); v-updates = 19 (loop) + 1 (tail)
#pragma unroll 1
    for (int it = 0; it < 19; ++it) {
        float z = dot64(xc, sU2);       // (X0^T u)_t
        float v; RCPF(v, z);
        sV[t] = v;
        __syncthreads();
        float y = dot64(xr, sV2);       // (X0 v)_t
        RCPF(u, y);
        sU[t] = u;
        __syncthreads();
    }
    {
        float z = dot64(xc, sU2);       // final column normalization (20th)
        float v; RCPF(v, z);
        sV[t] = v;
        __syncthreads();
    }

    // ---- epilogue: out[t][j] = u_t * X0[t][j] * v_j ----
    unsigned long long u2; PACK2(u2, u, u);
    float4* __restrict__ o4 = reinterpret_cast<float4*>(out) + (size_t)b * 1024 + t * 16;
#pragma unroll
    for (int k = 0; k < 16; k++) {
        ulonglong2 wv = sV2[k];
        unsigned long long p0, p1;
        MUL2(p0, xr[2 * k + 0], wv.x);
        MUL2(p0, p0, u2);
        MUL2(p1, xr[2 * k + 1], wv.y);
        MUL2(p1, p1, u2);
        float4 o;
        UNPACK2(o.x, o.y, p0);
        UNPACK2(o.z, o.w, p1);
        o4[k] = o;
    }
}

extern "C" void kernel_launch(void* const* d_in, const int* in_sizes, int n_in,
                              void* d_out, int out_size) {
    const float* gamma = (const float*)d_in[0];
    const float* noise = (const float*)d_in[1];
    int s0 = in_sizes[0], s1 = (n_in >= 2) ? in_sizes[1] : 0;
    if (s0 > s1) {  // defensive: gamma is the small one (4096 elements)
        const float* tmp = gamma; gamma = noise; noise = tmp;
        int ts = s0; s0 = s1; s1 = ts;
    }
    int num_matrices = s1 / 4096;  // 8192 for the reference shapes
    float* out = (float*)d_out;

    sigmoid_kernel<<<16, 256>>>(gamma);
    sinkhorn_kernel<<<num_matrices, 64>>>(noise, out);
}